// round 17
// baseline (speedup 1.0000x reference)
#include <cuda_runtime.h>
#include <cstdint>

// RadiusInteractionGraph: B=128 molecules x NPM=512 atoms, K=32 nearest
// neighbors within cutoff 10.0. One warp per center atom.
//
// R17: molecule-persistent blocks. 1024 blocks; each owns ONE molecule and
// loops over 4 center-groups of it. Positions staged ONCE per block; the
// group loop has NO barriers (slist/sres are warp-private, positions are
// read-only after the single __syncthreads) so warps free-run across
// groups — unlike R9's persistent loop, which re-staged a new molecule per
// iteration and paid a barrier convoy each time. Core build/sort/pop is the
// validated R16 champion structure.
//
// Output layout (float32): [ src (N*K) | dst (N*K) | weight (N*K) ]

#define BB   128
#define NPM  512
#define KK   32
#define NATOMS (BB * NPM)
#define NK   (NATOMS * KK)
#define WPB  16               // warps (centers) per group

#define FULLMASK 0xFFFFFFFFu
// Keys from d2<=100 are <= (bits(100.0f)|511) = 0x42C801FF; bucket 0x200.
#define VALID_LIMIT 0x42C80200u
#define PAD_KEY     0x7F000000u   // finite float, > any valid key

typedef unsigned long long ull;

// Packed f32x2 helpers (sm_100+ PTX; ptxas emits these only via PTX).
#define ADD2(o, a, b) asm("add.rn.f32x2 %0, %1, %2;" : "=l"(o) : "l"(a), "l"(b))
#define MUL2(o, a, b) asm("mul.rn.f32x2 %0, %1, %2;" : "=l"(o) : "l"(a), "l"(b))
#define FMA2(o, a, b, c) \
    asm("fma.rn.f32x2 %0, %1, %2, %3;" : "=l"(o) : "l"(a), "l"(b), "l"(c))
#define PACK2(o, lo, hi) \
    asm("mov.b64 %0, {%1, %2};" : "=l"(o) : "f"(lo), "f"(hi))
#define UNPACK2(lo, hi, in) \
    asm("mov.b64 {%0, %1}, %2;" : "=f"(lo), "=f"(hi) : "l"(in))

// Compare-exchange (ascending) on positive-float-pattern keys (FMNMX).
#define CAS(i, p) { const float a_ = fk[i], b_ = fk[p];                 \
                    fk[i] = fminf(a_, b_); fk[p] = fmaxf(a_, b_); }

// (d2bits & 0xFFFFFE00) | idx in ONE LOP3 (LUT 0xEA = (a&b)|c).
__device__ __forceinline__ unsigned int keypack(unsigned int d2bits,
                                                unsigned int idx) {
    unsigned int r;
    asm("lop3.b32 %0, %1, 0xFFFFFE00, %2, 0xEA;"
        : "=r"(r) : "r"(d2bits), "r"(idx));
    return r;
}

// One pop round with successor prefetch: winner consumes its prefetched
// h_next (no load on the critical path) and refills it for two wins ahead.
#define POP_ROUND(vc) {                                                  \
    const unsigned int m_ = __reduce_min_sync(FULLMASK, h);              \
    vc = m_;                                                             \
    if (h == m_) { h = h_next; addr += 32; h_next = addr[32]; } }

__global__ __launch_bounds__(512, 4)
void rig_topk_kernel(const float* __restrict__ pos, float* __restrict__ out)
{
    __shared__ float2       sxy[NPM];
    // z pair layout: szp[a] = (z_{j0}, z_{j0+32}) with j0 = (a>>5)*64+(a&31).
    // Inverse: atom j -> a = (j>>6)*32 + (j&31), half = (j>>5)&1.
    __shared__ float2       szp[NPM / 2];
    __shared__ unsigned int slist[WPB][18][32];  // [warp][entry][lane]
    __shared__ unsigned int sres[WPB][KK];       // [warp][rank]

    const int tid  = threadIdx.x;
    const int mol  = blockIdx.x >> 3;     // 8 blocks per molecule
    const int sub  = blockIdx.x & 7;      // this block's group quartet
    const int base = mol * NPM;

    // Stage this molecule's 512 positions ONCE: exactly 1 atom per thread.
    {
        const float* p = pos + (size_t)(base + tid) * 3;
        sxy[tid] = make_float2(p[0], p[1]);
        const int a  = ((tid >> 6) << 5) | (tid & 31);
        const int hl = (tid >> 5) & 1;
        reinterpret_cast<float*>(szp)[2 * a + hl] = p[2];
    }
    __syncthreads();   // the ONLY block barrier; loop below is barrier-free

    const int warp = tid >> 5;
    const int lane = tid & 31;
    const bool lead = (lane == 0);

    // 4 center-groups of this molecule. slist/sres rows are warp-private and
    // fully rewritten each iteration; positions are read-only -> no syncs.
#pragma unroll 1
    for (int it = 0; it < 4; it++) {
        const int n = (((sub << 2) + it) << 4) + warp;  // center in molecule
        const int g = base + n;                         // global center index

        const float2 cxy = sxy[n];
        const int an = ((n >> 6) << 5) | (n & 31);
        const int hn = (n >> 5) & 1;
        const float cz = reinterpret_cast<const float*>(szp)[2 * an + hn];
        ull ncxy, nczz;
        PACK2(ncxy, -cxy.x, -cxy.y);
        PACK2(nczz, -cz, -cz);

        // Each lane owns 16 candidates: j = lane + 32*t, as 8 pairs
        // (j0 = lane + tp*64, j1 = j0 + 32); dz for both from ONE LDS.64.
        // Key = (d2 bits, low 9 mantissa bits cleared) | index (one LOP3).
        // Positive float pattern: float order == uint order == (d2, idx).
        // Self: x + (-x) = +0 (RN) each term -> d2 == +0 -> key == n < 512:
        // the warp's strict minimum. Cutoff handled at decode.
        float fk[16];
#pragma unroll
        for (int tp = 0; tp < 8; tp++) {
            const int j0 = lane + (tp << 6);
            const int j1 = j0 + 32;
            const ull q0 = *reinterpret_cast<const ull*>(&sxy[j0]);
            const ull q1 = *reinterpret_cast<const ull*>(&sxy[j1]);
            const ull zz = *reinterpret_cast<const ull*>(&szp[(tp << 5) + lane]);

            ull dxy0, dxy1, dzz;
            ADD2(dxy0, q0, ncxy);
            ADD2(dxy1, q1, ncxy);
            ADD2(dzz, zz, nczz);
            ull s0, s1;
            MUL2(s0, dxy0, dxy0);
            MUL2(s1, dxy1, dxy1);
            float s0x, s0y, s1x, s1y;
            UNPACK2(s0x, s0y, s0);
            UNPACK2(s1x, s1y, s1);
            const float h0 = s0x + s0y;
            const float h1 = s1x + s1y;
            ull hp;  PACK2(hp, h0, h1);
            ull d2p;
            FMA2(d2p, dzz, dzz, hp);
            float d20, d21;
            UNPACK2(d20, d21, d2p);

            fk[2 * tp]     = __uint_as_float(
                keypack(__float_as_uint(d20), (unsigned int)j0));
            fk[2 * tp + 1] = __uint_as_float(
                keypack(__float_as_uint(d21), (unsigned int)j1));
        }

        // Batcher merge-exchange network for 16 (63 CAS), ascending.
        CAS(0,8)  CAS(1,9)  CAS(2,10) CAS(3,11) CAS(4,12) CAS(5,13) CAS(6,14) CAS(7,15)
        CAS(0,4)  CAS(1,5)  CAS(2,6)  CAS(3,7)  CAS(8,12) CAS(9,13) CAS(10,14) CAS(11,15)
        CAS(4,8)  CAS(5,9)  CAS(6,10) CAS(7,11)
        CAS(0,2)  CAS(1,3)  CAS(4,6)  CAS(5,7)  CAS(8,10) CAS(9,11) CAS(12,14) CAS(13,15)
        CAS(2,8)  CAS(3,9)  CAS(6,12) CAS(7,13)
        CAS(2,4)  CAS(3,5)  CAS(6,8)  CAS(7,9)  CAS(10,12) CAS(11,13)
        CAS(0,1)  CAS(2,3)  CAS(4,5)  CAS(6,7)  CAS(8,9)  CAS(10,11) CAS(12,13) CAS(14,15)
        CAS(1,8)  CAS(3,10) CAS(5,12) CAS(7,14)
        CAS(1,4)  CAS(3,6)  CAS(5,8)  CAS(7,10) CAS(9,12) CAS(11,14)
        CAS(1,2)  CAS(3,4)  CAS(5,6)  CAS(7,8)  CAS(9,10) CAS(11,12) CAS(13,14)

        // Spill entries 2..15 + two pads. Entries 0/1 never loaded from SMEM
        // (h/h_next start in registers; first SMEM load targets entry 2).
#pragma unroll
        for (int t = 2; t < 16; t++)
            slist[warp][t][lane] = __float_as_uint(fk[t]);
        slist[warp][16][lane] = PAD_KEY;
        slist[warp][17][lane] = PAD_KEY;

        // Pre-skip the self-edge (register-based): self is the self-lane's
        // sorted position 0 and the guaranteed warp minimum.
        const unsigned int* addr = &slist[warp][0][lane];
        unsigned int h      = __float_as_uint(fk[0]);
        unsigned int h_next = __float_as_uint(fk[1]);
        if (lane == (n & 31)) {
            h = __float_as_uint(fk[1]);
            h_next = __float_as_uint(fk[2]);
            addr += 32;
        }

        // Pop-merge: 32 rounds in 8 groups of 4; leader stores 4 ranks with
        // one STS.128. m is always a real key (pads lose within 33 pops of
        // 512), keys unique -> exactly one lane advances per round; each
        // lane advances <= 16 times, prefetch reads at most entry 17.
#pragma unroll
        for (int rq = 0; rq < 8; rq++) {
            uint4 v;
            POP_ROUND(v.x)
            POP_ROUND(v.y)
            POP_ROUND(v.z)
            POP_ROUND(v.w)
            if (lead) *(uint4*)&sres[warp][rq << 2] = v;
        }
        __syncwarp();
        const unsigned int myres = sres[warp][lane];

        // Decode + write. lane == rank; edges for one warp contiguous.
        const bool valid = (myres < VALID_LIMIT);
        const int  j     = (int)(myres & 511u);
        const float d2q  = __uint_as_float(myres & 0xFFFFFE00u);
        float ws;
        asm("sqrt.approx.f32 %0, %1;" : "=f"(ws) : "f"(d2q));

        const int e    = g * KK + lane;
        const int isrc = valid ? (base + j) : g;
        const float w  = valid ? ws : 0.0f;

        out[e]          = (float)isrc;   // edge_index row 0 (src)
        out[NK + e]     = (float)g;      // edge_index row 1 (dst)
        out[2 * NK + e] = w;             // edge_weight
    }
}

extern "C" void kernel_launch(void* const* d_in, const int* in_sizes, int n_in,
                              void* d_out, int out_size)
{
    const float* pos = (const float*)d_in[0];
    // d_in[1] (batch) is structurally known: repeat(arange(128), 512) -> unused.
    float* out = (float*)d_out;

    // 1024 blocks x 512 threads: 8 blocks/molecule, 4 center-groups/block,
    // positions staged once per block, barrier-free group loop.
    rig_topk_kernel<<<BB * 8, 512>>>(pos, out);
}